// round 1
// baseline (speedup 1.0000x reference)
#include <cuda_runtime.h>
#include <stdint.h>

// Problem constants
#define B_   32
#define C_   128
#define H_   56
#define W_   56
#define O_   256
#define HW_  (H_*W_)           // 3136
#define NPOS (B_*HW_)          // 100352
#define KTOT (C_*9)            // 1152

// Scratch (allocation-free rule: __device__ globals)
__device__ __align__(16) int8_t g_qx[NPOS * C_];        // [b*HW + h*W + w][c]  (NHWC)
__device__ __align__(16) int8_t g_qw[O_ * KTOT];        // [o][kp][c]
__device__ float g_sw[O_];

// ---------------------------------------------------------------------------
// 1) Quantize x: NCHW fp32 -> NHWC int8.  One thread per spatial position,
//    loops over all 128 channels (reads coalesced across lanes per channel),
//    packs 4 int8 per int, writes 128B contiguous per thread via int4.
// ---------------------------------------------------------------------------
__global__ void quant_x_kernel(const float* __restrict__ x,
                               const float* __restrict__ scale_x_p)
{
    int pos = blockIdx.x * 128 + threadIdx.x;      // grid = 784*128 == NPOS exactly
    float s = *scale_x_p;
    int b  = pos / HW_;
    int sp = pos - b * HW_;
    const float* xp = x + (size_t)b * C_ * HW_ + sp;   // channel c at xp[c*HW_]

    int4 outv[8];
#pragma unroll
    for (int g = 0; g < 8; g++) {
        int lane[4];
#pragma unroll
        for (int q = 0; q < 4; q++) {
            int pack = 0;
#pragma unroll
            for (int bb = 0; bb < 4; bb++) {
                int c = g * 16 + q * 4 + bb;
                float v = xp[c * HW_];
                int qi = (int)rintf(v / s);        // true div + RNE == jnp.round(x/s)
                qi = max(-127, min(127, qi));
                pack |= (qi & 0xFF) << (8 * bb);
            }
            lane[q] = pack;
        }
        outv[g] = make_int4(lane[0], lane[1], lane[2], lane[3]);
    }
    int4* dst = (int4*)(g_qx + (size_t)pos * C_);
#pragma unroll
    for (int g = 0; g < 8; g++) dst[g] = outv[g];
}

// ---------------------------------------------------------------------------
// 2) Weight quantization: per-output-channel dynamic scale = max|w|/127,
//    layout repack [O][C][3][3] -> [O][kp][C] int8.
// ---------------------------------------------------------------------------
__global__ void quant_w_kernel(const float* __restrict__ w)
{
    int o = blockIdx.x;
    int t = threadIdx.x;          // 128 threads
    const float* wo = w + (size_t)o * KTOT;

    float m = 0.f;
    for (int i = t; i < KTOT; i += 128) m = fmaxf(m, fabsf(wo[i]));
#pragma unroll
    for (int off = 16; off; off >>= 1)
        m = fmaxf(m, __shfl_xor_sync(0xFFFFFFFFu, m, off));
    __shared__ float red[4];
    if ((t & 31) == 0) red[t >> 5] = m;
    __syncthreads();
    m = fmaxf(fmaxf(red[0], red[1]), fmaxf(red[2], red[3]));
    float scale = m / 127.0f;
    if (t == 0) g_sw[o] = scale;

    for (int i = t; i < KTOT; i += 128) {
        int c = i / 9, kp = i - c * 9;
        int qi = (int)rintf(wo[i] / scale);
        qi = max(-127, min(127, qi));
        g_qw[(size_t)o * KTOT + kp * C_ + c] = (int8_t)qi;
    }
}

// ---------------------------------------------------------------------------
// 3) dp4a implicit-GEMM conv.
//    Block tile: 64 spatial positions x 64 output channels, 128 threads.
//    Thread: 4 positions (tx + 16*pi) x 8 channels (ty + 8*oi) = 32 int32 accs.
//    smem padded to 33 ints/row -> all LDS conflict-free (distinct banks or
//    broadcast within each instruction).
// ---------------------------------------------------------------------------
#define TS 64
#define TO 64

__global__ __launch_bounds__(128)
void conv_dp4a_kernel(const float* __restrict__ scale_x_p,
                      const float* __restrict__ bias,
                      float* __restrict__ out)
{
    __shared__ int xs[TS * 33];
    __shared__ int ws[TO * 33];

    const int* qx_i = (const int*)g_qx;   // 32 ints per position
    const int* qw_i = (const int*)g_qw;   // 288 ints per o (9*32)

    int t  = threadIdx.x;
    int tx = t & 15;
    int ty = t >> 4;                      // 0..7
    int s0 = blockIdx.x * TS;             // 3136 % 64 == 0 -> single batch per block
    int o0 = blockIdx.y * TO;
    int b   = s0 / HW_;
    int sp0 = s0 - b * HW_;

    int acc[4][8];
#pragma unroll
    for (int pi = 0; pi < 4; pi++)
#pragma unroll
        for (int oi = 0; oi < 8; oi++) acc[pi][oi] = 0;

    for (int kp = 0; kp < 9; kp++) {
        int kh = kp / 3, kw = kp - kh * 3;

        // Load x tile: TS positions x 32 ints (2048 ints / 128 threads = 16 each)
#pragma unroll
        for (int i = 0; i < 16; i++) {
            int idx = t + 128 * i;
            int p = idx >> 5, j = idx & 31;
            int sp = sp0 + p;
            int oh = sp / W_;
            int ow = sp - oh * W_;
            int ih = oh + kh - 1;
            int iw = ow + kw - 1;
            int v = 0;
            if (ih >= 0 && ih < H_ && iw >= 0 && iw < W_)
                v = qx_i[((size_t)b * HW_ + ih * W_ + iw) * 32 + j];
            xs[p * 33 + j] = v;
        }
        // Load w tile: TO channels x 32 ints
#pragma unroll
        for (int i = 0; i < 16; i++) {
            int idx = t + 128 * i;
            int ol = idx >> 5, j = idx & 31;
            ws[ol * 33 + j] = qw_i[(size_t)(o0 + ol) * 288 + kp * 32 + j];
        }
        __syncthreads();

#pragma unroll 4
        for (int j = 0; j < 32; j++) {
            int xv[4], wv[8];
#pragma unroll
            for (int pi = 0; pi < 4; pi++) xv[pi] = xs[(tx + 16 * pi) * 33 + j];
#pragma unroll
            for (int oi = 0; oi < 8; oi++) wv[oi] = ws[(ty + 8 * oi) * 33 + j];
#pragma unroll
            for (int pi = 0; pi < 4; pi++)
#pragma unroll
                for (int oi = 0; oi < 8; oi++)
                    acc[pi][oi] = __dp4a(xv[pi], wv[oi], acc[pi][oi]);
        }
        __syncthreads();
    }

    // Epilogue: dequant + bias, NCHW output
    float sx = *scale_x_p;
#pragma unroll
    for (int oi = 0; oi < 8; oi++) {
        int o = o0 + ty + 8 * oi;
        float sc = sx * g_sw[o];
        float bo = bias[o];
        size_t obase = ((size_t)b * O_ + o) * HW_ + sp0;
#pragma unroll
        for (int pi = 0; pi < 4; pi++) {
            int p = tx + 16 * pi;
            out[obase + p] = (float)acc[pi][oi] * sc + bo;
        }
    }
}

// ---------------------------------------------------------------------------
extern "C" void kernel_launch(void* const* d_in, const int* in_sizes, int n_in,
                              void* d_out, int out_size)
{
    const float* x       = (const float*)d_in[0];   // [32,128,56,56]
    const float* weight  = (const float*)d_in[1];   // [256,128,3,3]
    const float* bias    = (const float*)d_in[2];   // [256]
    const float* scale_x = (const float*)d_in[3];   // scalar
    // d_in[4] = lut (unused: dp4a gives exact int arithmetic)
    float* out = (float*)d_out;

    quant_x_kernel<<<NPOS / 128, 128>>>(x, scale_x);
    quant_w_kernel<<<O_, 128>>>(weight);

    dim3 grid(NPOS / TS, O_ / TO);   // (1568, 4)
    conv_dp4a_kernel<<<grid, 128>>>(scale_x, bias, out);
}

// round 3
// speedup vs baseline: 1.1012x; 1.1012x over previous
#include <cuda_runtime.h>
#include <stdint.h>

// Problem constants
#define B_   32
#define C_   128
#define H_   56
#define W_   56
#define O_   256
#define HW_  (H_*W_)           // 3136
#define NPOS (B_*HW_)          // 100352

// Scratch (__device__ globals, allocation-free rule)
__device__ __align__(16) int8_t g_qx[(size_t)NPOS * C_];       // [pos][c] NHWC int8
__device__ __align__(16) int8_t g_qw[(size_t)O_ * 9 * C_];     // [o][kp][c] int8
__device__ float g_sw[O_];

// ---------------------------------------------------------------------------
// PTX helpers (all legacy-path: valid on plain sm_103 target)
// ---------------------------------------------------------------------------
__device__ __forceinline__ void cp16(uint32_t dst, const void* src, uint32_t sz) {
    asm volatile("cp.async.cg.shared.global [%0], [%1], 16, %2;\n"
                 :: "r"(dst), "l"(__cvta_generic_to_global(src)), "r"(sz));
}
__device__ __forceinline__ void cp_commit() { asm volatile("cp.async.commit_group;\n" ::); }
template<int N> __device__ __forceinline__ void cp_wait() {
    asm volatile("cp.async.wait_group %0;\n" :: "n"(N));
}
__device__ __forceinline__ void ldsm4(uint32_t* r, uint32_t addr) {
    asm volatile("ldmatrix.sync.aligned.m8n8.x4.shared.b16 {%0,%1,%2,%3}, [%4];\n"
                 : "=r"(r[0]), "=r"(r[1]), "=r"(r[2]), "=r"(r[3]) : "r"(addr));
}
__device__ __forceinline__ void mma_s8(int* c, const uint32_t* a, uint32_t b0, uint32_t b1) {
    asm volatile("mma.sync.aligned.m16n8k32.row.col.s32.s8.s8.s32 "
                 "{%0,%1,%2,%3}, {%4,%5,%6,%7}, {%8,%9}, {%0,%1,%2,%3};\n"
                 : "+r"(c[0]), "+r"(c[1]), "+r"(c[2]), "+r"(c[3])
                 : "r"(a[0]), "r"(a[1]), "r"(a[2]), "r"(a[3]), "r"(b0), "r"(b1));
}

// ---------------------------------------------------------------------------
// 1) Quantize x: NCHW fp32 -> NHWC int8. 4 threads per position (32 ch each).
// ---------------------------------------------------------------------------
__global__ __launch_bounds__(256) void quant_x_kernel(const float* __restrict__ x,
                                                      const float* __restrict__ sxp)
{
    int gid = blockIdx.x * 256 + threadIdx.x;   // NPOS*4 threads
    float s = *sxp;
    int pos = gid >> 2, g = gid & 3;
    int b = pos / HW_, sp = pos - b * HW_;
    const float* xp = x + (size_t)b * C_ * HW_ + (size_t)(g * 32) * HW_ + sp;

    uint32_t pk[8];
#pragma unroll
    for (int q = 0; q < 8; q++) {
        uint32_t p = 0;
#pragma unroll
        for (int bb = 0; bb < 4; bb++) {
            float v = xp[(q * 4 + bb) * HW_];
            int qi = (int)rintf(v / s);          // true div + RNE == jnp.round(x/s)
            qi = max(-127, min(127, qi));
            p |= (uint32_t)(qi & 0xFF) << (8 * bb);
        }
        pk[q] = p;
    }
    uint4* dst = (uint4*)(g_qx + (size_t)pos * C_ + g * 32);
    dst[0] = make_uint4(pk[0], pk[1], pk[2], pk[3]);
    dst[1] = make_uint4(pk[4], pk[5], pk[6], pk[7]);
}

// ---------------------------------------------------------------------------
// 2) Weight quantization: per-o scale = max|w|/127, repack [O][C][3][3]->[o][kp][c]
// ---------------------------------------------------------------------------
__global__ __launch_bounds__(128) void quant_w_kernel(const float* __restrict__ w)
{
    int o = blockIdx.x, t = threadIdx.x;
    const float* wo = w + (size_t)o * 1152;

    float m = 0.f;
    for (int i = t; i < 1152; i += 128) m = fmaxf(m, fabsf(wo[i]));
#pragma unroll
    for (int off = 16; off; off >>= 1) m = fmaxf(m, __shfl_xor_sync(0xFFFFFFFFu, m, off));
    __shared__ float red[4];
    if ((t & 31) == 0) red[t >> 5] = m;
    __syncthreads();
    m = fmaxf(fmaxf(red[0], red[1]), fmaxf(red[2], red[3]));
    float scale = m / 127.0f;
    if (t == 0) g_sw[o] = scale;

    for (int i = t; i < 1152; i += 128) {
        int c = i / 9, kp = i - c * 9;
        int q = (int)rintf(wo[i] / scale);
        q = max(-127, min(127, q));
        g_qw[((size_t)o * 9 + kp) * C_ + c] = (int8_t)q;
    }
}

// ---------------------------------------------------------------------------
// 3) IMMA implicit-GEMM conv.
//    CTA: 128 positions x 256 o, 512 threads. Warp (wm,wn): 32 pos x 64 o.
//    Per tap: stage A(128x128B)+B(256x128B) int8, stride 144B (conflict-free
//    ldmatrix), double-buffered cp.async; 4 k32-steps, 16 mma/warp/step.
// ---------------------------------------------------------------------------
#define ASTRIDE 144
#define ABYTES  (128 * ASTRIDE)       // 18432
#define BBYTES  (256 * ASTRIDE)       // 36864
#define STAGE   (ABYTES + BBYTES)     // 55296
#define SMEM_DYN (2 * STAGE)          // 110592

__global__ __launch_bounds__(512)
void conv_imma_kernel(const float* __restrict__ sxp,
                      const float* __restrict__ bias,
                      float* __restrict__ out)
{
    extern __shared__ char sm[];
    uint32_t sbase = (uint32_t)__cvta_generic_to_shared(sm);
    int t = threadIdx.x;
    int wid = t >> 5, l = t & 31;
    int wm = wid >> 2, wn = wid & 3;
    int s0 = blockIdx.x * 128;

    // Load geometry: thread owns A rows {t>>3, t>>3+64}, chunk j = t&7
    int jj = t & 7;
    int bA[2], ohA[2], owA[2];
#pragma unroll
    for (int i = 0; i < 2; i++) {
        int r = (t >> 3) + 64 * i;
        int pos = s0 + r;
        int b = pos / HW_, sp = pos - b * HW_;
        bA[i] = b; ohA[i] = sp / W_; owA[i] = sp - ohA[i] * W_;
    }

    int acc[2][8][4];
#pragma unroll
    for (int mi = 0; mi < 2; mi++)
#pragma unroll
        for (int ni = 0; ni < 8; ni++)
#pragma unroll
            for (int q = 0; q < 4; q++) acc[mi][ni][q] = 0;

    auto load_stage = [&](int kp, int stg) {
        uint32_t Ab = sbase + stg * STAGE;
        uint32_t Bb = Ab + ABYTES;
        int kh = kp / 3, kw = kp - kh * 3;
#pragma unroll
        for (int i = 0; i < 2; i++) {
            int r = (t >> 3) + 64 * i;
            int ih = ohA[i] + kh - 1, iw = owA[i] + kw - 1;
            bool v = ((unsigned)ih < (unsigned)H_) && ((unsigned)iw < (unsigned)W_);
            const int8_t* src = v
                ? (g_qx + ((size_t)bA[i] * HW_ + (size_t)ih * W_ + iw) * C_ + jj * 16)
                : g_qx;
            cp16(Ab + r * ASTRIDE + jj * 16, src, v ? 16u : 0u);
        }
#pragma unroll
        for (int i = 0; i < 4; i++) {
            int o = (t >> 3) + 64 * i;
            const int8_t* src = g_qw + ((size_t)o * 9 + kp) * C_ + jj * 16;
            cp16(Bb + o * ASTRIDE + jj * 16, src, 16u);
        }
    };

    auto compute_stage = [&](int stg) {
        uint32_t Ab = sbase + stg * STAGE;
        uint32_t Bb = Ab + ABYTES;
        uint32_t aAddr[2], bAddr[4];
#pragma unroll
        for (int mi = 0; mi < 2; mi++) {
            int r = wm * 32 + mi * 16 + (l & 15);
            aAddr[mi] = Ab + r * ASTRIDE + (l >> 4) * 16;
        }
#pragma unroll
        for (int p = 0; p < 4; p++) {
            int o = wn * 64 + p * 16 + (l & 7) + (l >> 4) * 8;
            bAddr[p] = Bb + o * ASTRIDE + ((l >> 3) & 1) * 16;
        }
#pragma unroll
        for (int ks = 0; ks < 4; ks++) {
            uint32_t a[2][4];
            ldsm4(a[0], aAddr[0] + ks * 32);
            ldsm4(a[1], aAddr[1] + ks * 32);
            uint32_t bf[4][4];
#pragma unroll
            for (int p = 0; p < 4; p++) ldsm4(bf[p], bAddr[p] + ks * 32);
#pragma unroll
            for (int mi = 0; mi < 2; mi++)
#pragma unroll
                for (int ni = 0; ni < 8; ni++) {
                    const uint32_t* bb = bf[ni >> 1];
                    uint32_t b0 = (ni & 1) ? bb[2] : bb[0];
                    uint32_t b1 = (ni & 1) ? bb[3] : bb[1];
                    mma_s8(acc[mi][ni], a[mi], b0, b1);
                }
        }
    };

    load_stage(0, 0);
    cp_commit();
#pragma unroll 1
    for (int kp = 0; kp < 9; kp++) {
        if (kp < 8) {
            load_stage(kp + 1, (kp + 1) & 1);
            cp_commit();
            cp_wait<1>();
        } else {
            cp_wait<0>();
        }
        __syncthreads();
        compute_stage(kp & 1);
        __syncthreads();   // protect buffer before kp+2 load overwrites it
    }

    // Epilogue: dequant + bias, NCHW out.
    // C frag m16n8: lane l (g=l>>2, tg=l&3): c0=[g][2tg] c1=[g][2tg+1] c2=[g+8][2tg] c3=[g+8][2tg+1]
    float sx = *sxp;
    int g = l >> 2, tg = l & 3;
#pragma unroll
    for (int mi = 0; mi < 2; mi++) {
#pragma unroll
        for (int h = 0; h < 2; h++) {
            int r = wm * 32 + mi * 16 + g + 8 * h;
            int pos = s0 + r;
            int b = pos / HW_, sp = pos - b * HW_;
#pragma unroll
            for (int ni = 0; ni < 8; ni++) {
                int o = wn * 64 + ni * 8 + tg * 2;
                float f0 = (float)acc[mi][ni][h * 2 + 0];
                float f1 = (float)acc[mi][ni][h * 2 + 1];
                out[((size_t)b * O_ + o) * HW_ + sp]       = f0 * (sx * g_sw[o])     + bias[o];
                out[((size_t)b * O_ + o + 1) * HW_ + sp]   = f1 * (sx * g_sw[o + 1]) + bias[o + 1];
            }
        }
    }
}

// ---------------------------------------------------------------------------
extern "C" void kernel_launch(void* const* d_in, const int* in_sizes, int n_in,
                              void* d_out, int out_size)
{
    const float* x       = (const float*)d_in[0];   // [32,128,56,56]
    const float* weight  = (const float*)d_in[1];   // [256,128,3,3]
    const float* bias    = (const float*)d_in[2];   // [256]
    const float* scale_x = (const float*)d_in[3];   // scalar
    // d_in[4] = lut (unused; IMMA arithmetic is exact)
    float* out = (float*)d_out;

    cudaFuncSetAttribute(conv_imma_kernel,
                         cudaFuncAttributeMaxDynamicSharedMemorySize, SMEM_DYN);

    quant_x_kernel<<<NPOS * 4 / 256, 256>>>(x, scale_x);
    quant_w_kernel<<<O_, 128>>>(weight);
    conv_imma_kernel<<<NPOS / 128, 512, SMEM_DYN>>>(scale_x, bias, out);
}

// round 4
// speedup vs baseline: 2.2677x; 2.0593x over previous
#include <cuda_runtime.h>
#include <cuda_bf16.h>
#include <stdint.h>

// Problem constants
#define B_   32
#define C_   128
#define H_   56
#define W_   56
#define O_   256
#define HW_  (H_*W_)           // 3136
#define NPOS (B_*HW_)          // 100352

// Scratch (__device__ globals, allocation-free rule)
__device__ __align__(16) __nv_bfloat16 g_xb[(size_t)NPOS * C_];     // [pos][c] NHWC bf16
__device__ __align__(16) __nv_bfloat16 g_wb[(size_t)O_ * 9 * C_];   // [o][kp][c] bf16
__device__ float g_sw[O_];

// ---------------------------------------------------------------------------
// PTX helpers (base-ISA only; valid on plain sm_103 target)
// ---------------------------------------------------------------------------
__device__ __forceinline__ void cp16(uint32_t dst, const void* src, uint32_t sz) {
    asm volatile("cp.async.cg.shared.global [%0], [%1], 16, %2;\n"
                 :: "r"(dst), "l"(__cvta_generic_to_global(src)), "r"(sz));
}
__device__ __forceinline__ void cp_commit() { asm volatile("cp.async.commit_group;\n" ::); }
template<int N> __device__ __forceinline__ void cp_wait() {
    asm volatile("cp.async.wait_group %0;\n" :: "n"(N));
}
__device__ __forceinline__ void ldsm4(uint32_t* r, uint32_t addr) {
    asm volatile("ldmatrix.sync.aligned.m8n8.x4.shared.b16 {%0,%1,%2,%3}, [%4];\n"
                 : "=r"(r[0]), "=r"(r[1]), "=r"(r[2]), "=r"(r[3]) : "r"(addr));
}
__device__ __forceinline__ void mma_bf16(float* c, const uint32_t* a, uint32_t b0, uint32_t b1) {
    asm volatile("mma.sync.aligned.m16n8k16.row.col.f32.bf16.bf16.f32 "
                 "{%0,%1,%2,%3}, {%4,%5,%6,%7}, {%8,%9}, {%0,%1,%2,%3};\n"
                 : "+f"(c[0]), "+f"(c[1]), "+f"(c[2]), "+f"(c[3])
                 : "r"(a[0]), "r"(a[1]), "r"(a[2]), "r"(a[3]), "r"(b0), "r"(b1));
}

// ---------------------------------------------------------------------------
// 1) Quantize x: NCHW fp32 -> NHWC bf16 (integer-valued). 4 threads/pos.
// ---------------------------------------------------------------------------
__global__ __launch_bounds__(256) void quant_x_kernel(const float* __restrict__ x,
                                                      const float* __restrict__ sxp)
{
    int gid = blockIdx.x * 256 + threadIdx.x;   // NPOS*4 threads
    float s = *sxp;
    int pos = gid >> 2, g = gid & 3;
    int b = pos / HW_, sp = pos - b * HW_;
    const float* xp = x + (size_t)b * C_ * HW_ + (size_t)(g * 32) * HW_ + sp;

    uint32_t pk[16];
#pragma unroll
    for (int j = 0; j < 16; j++) {
        float v0 = xp[(2 * j) * HW_], v1 = xp[(2 * j + 1) * HW_];
        int q0 = (int)rintf(v0 / s); q0 = max(-127, min(127, q0));
        int q1 = (int)rintf(v1 / s); q1 = max(-127, min(127, q1));
        __nv_bfloat162 h = __floats2bfloat162_rn((float)q0, (float)q1);
        pk[j] = *(uint32_t*)&h;
    }
    uint4* dst = (uint4*)(g_xb + (size_t)pos * C_ + g * 32);
#pragma unroll
    for (int q = 0; q < 4; q++)
        dst[q] = make_uint4(pk[4 * q], pk[4 * q + 1], pk[4 * q + 2], pk[4 * q + 3]);
}

// ---------------------------------------------------------------------------
// 2) Weight quantization: per-o scale = max|w|/127, repack [O][C][3][3]->[o][kp][c] bf16
// ---------------------------------------------------------------------------
__global__ __launch_bounds__(128) void quant_w_kernel(const float* __restrict__ w)
{
    int o = blockIdx.x, t = threadIdx.x;
    const float* wo = w + (size_t)o * 1152;

    float m = 0.f;
    for (int i = t; i < 1152; i += 128) m = fmaxf(m, fabsf(wo[i]));
#pragma unroll
    for (int off = 16; off; off >>= 1) m = fmaxf(m, __shfl_xor_sync(0xFFFFFFFFu, m, off));
    __shared__ float red[4];
    if ((t & 31) == 0) red[t >> 5] = m;
    __syncthreads();
    m = fmaxf(fmaxf(red[0], red[1]), fmaxf(red[2], red[3]));
    float scale = m / 127.0f;
    if (t == 0) g_sw[o] = scale;

    for (int i = t; i < 1152; i += 128) {
        int c = i / 9, kp = i - c * 9;
        int q = (int)rintf(wo[i] / scale);
        q = max(-127, min(127, q));
        g_wb[((size_t)o * 9 + kp) * C_ + c] = __float2bfloat16((float)q);
    }
}

// ---------------------------------------------------------------------------
// 3) bf16 HMMA implicit-GEMM conv.
//    CTA: 128 positions x 256 o, 512 threads. Warp (wm,wn): 32 pos x 64 o.
//    18 stages (9 taps x 2 channel-halves of 64). Stage: A 128x128B,
//    B 256x128B bf16, stride 144B (conflict-free ldmatrix), double-buffered.
//    Per k16 step/warp: 2 A-ldsm + 4 B-ldsm + 16 mma.m16n8k16.bf16.f32.
// ---------------------------------------------------------------------------
#define ASTRIDE 144
#define ABYTES  (128 * ASTRIDE)       // 18432
#define BBYTES  (256 * ASTRIDE)       // 36864
#define STAGE   (ABYTES + BBYTES)     // 55296
#define SMEM_DYN (2 * STAGE)          // 110592

__global__ __launch_bounds__(512)
void conv_hmma_kernel(const float* __restrict__ sxp,
                      const float* __restrict__ bias,
                      float* __restrict__ out)
{
    extern __shared__ char sm[];
    uint32_t sbase = (uint32_t)__cvta_generic_to_shared(sm);
    int t = threadIdx.x;
    int wid = t >> 5, l = t & 31;
    int wm = wid >> 2, wn = wid & 3;
    int s0 = blockIdx.x * 128;

    // Load geometry: thread owns A rows {t>>3, t>>3+64}, 16B chunk jj = t&7
    int jj = t & 7;
    int bA[2], ohA[2], owA[2];
#pragma unroll
    for (int i = 0; i < 2; i++) {
        int r = (t >> 3) + 64 * i;
        int pos = s0 + r;
        int b = pos / HW_, sp = pos - b * HW_;
        bA[i] = b; ohA[i] = sp / W_; owA[i] = sp - ohA[i] * W_;
    }

    float acc[2][8][4];
#pragma unroll
    for (int mi = 0; mi < 2; mi++)
#pragma unroll
        for (int ni = 0; ni < 8; ni++)
#pragma unroll
            for (int q = 0; q < 4; q++) acc[mi][ni][q] = 0.f;

    auto load_stage = [&](int s, int stg) {
        int kp = s >> 1, half = s & 1;
        uint32_t Ab = sbase + stg * STAGE;
        uint32_t Bb = Ab + ABYTES;
        int kh = kp / 3, kw = kp - kh * 3;
        int coff = half * 64 + jj * 8;            // channel offset of this 16B chunk
#pragma unroll
        for (int i = 0; i < 2; i++) {
            int r = (t >> 3) + 64 * i;
            int ih = ohA[i] + kh - 1, iw = owA[i] + kw - 1;
            bool v = ((unsigned)ih < (unsigned)H_) && ((unsigned)iw < (unsigned)W_);
            const __nv_bfloat16* src = v
                ? (g_xb + ((size_t)bA[i] * HW_ + (size_t)ih * W_ + iw) * C_ + coff)
                : g_xb;
            cp16(Ab + r * ASTRIDE + jj * 16, src, v ? 16u : 0u);
        }
#pragma unroll
        for (int i = 0; i < 4; i++) {
            int o = (t >> 3) + 64 * i;
            const __nv_bfloat16* src = g_wb + ((size_t)o * 9 + kp) * C_ + coff;
            cp16(Bb + o * ASTRIDE + jj * 16, src, 16u);
        }
    };

    auto compute_stage = [&](int stg) {
        uint32_t Ab = sbase + stg * STAGE;
        uint32_t Bb = Ab + ABYTES;
        uint32_t aAddr[2], bAddr[4];
#pragma unroll
        for (int mi = 0; mi < 2; mi++) {
            int r = wm * 32 + mi * 16 + (l & 15);
            aAddr[mi] = Ab + r * ASTRIDE + (l >> 4) * 16;
        }
#pragma unroll
        for (int p = 0; p < 4; p++) {
            int o = wn * 64 + p * 16 + (l & 7) + (l >> 4) * 8;
            bAddr[p] = Bb + o * ASTRIDE + ((l >> 3) & 1) * 16;
        }
#pragma unroll
        for (int ks = 0; ks < 4; ks++) {          // 4 x k16 = 64 channels
            uint32_t a[2][4];
            ldsm4(a[0], aAddr[0] + ks * 32);
            ldsm4(a[1], aAddr[1] + ks * 32);
            uint32_t bf[4][4];
#pragma unroll
            for (int p = 0; p < 4; p++) ldsm4(bf[p], bAddr[p] + ks * 32);
#pragma unroll
            for (int mi = 0; mi < 2; mi++)
#pragma unroll
                for (int ni = 0; ni < 8; ni++) {
                    const uint32_t* bb = bf[ni >> 1];
                    uint32_t b0 = (ni & 1) ? bb[2] : bb[0];
                    uint32_t b1 = (ni & 1) ? bb[3] : bb[1];
                    mma_bf16(acc[mi][ni], a[mi], b0, b1);
                }
        }
    };

    load_stage(0, 0);
    cp_commit();
#pragma unroll 1
    for (int s = 0; s < 18; s++) {
        if (s < 17) {
            load_stage(s + 1, (s + 1) & 1);
            cp_commit();
            cp_wait<1>();
        } else {
            cp_wait<0>();
        }
        __syncthreads();
        compute_stage(s & 1);
        __syncthreads();   // protect buffer before s+2 load overwrites it
    }

    // Epilogue: dequant + bias, NCHW out.
    // C frag m16n8: lane l (g=l>>2, tg=l&3): c0=[g][2tg] c1=[g][2tg+1] c2=[g+8][2tg] c3=[g+8][2tg+1]
    float sx = *sxp;
    int g = l >> 2, tg = l & 3;
#pragma unroll
    for (int mi = 0; mi < 2; mi++) {
#pragma unroll
        for (int h = 0; h < 2; h++) {
            int r = wm * 32 + mi * 16 + g + 8 * h;
            int pos = s0 + r;
            int b = pos / HW_, sp = pos - b * HW_;
#pragma unroll
            for (int ni = 0; ni < 8; ni++) {
                int o = wn * 64 + ni * 8 + tg * 2;
                float f0 = acc[mi][ni][h * 2 + 0];
                float f1 = acc[mi][ni][h * 2 + 1];
                out[((size_t)b * O_ + o) * HW_ + sp]     = f0 * (sx * g_sw[o])     + bias[o];
                out[((size_t)b * O_ + o + 1) * HW_ + sp] = f1 * (sx * g_sw[o + 1]) + bias[o + 1];
            }
        }
    }
}

// ---------------------------------------------------------------------------
extern "C" void kernel_launch(void* const* d_in, const int* in_sizes, int n_in,
                              void* d_out, int out_size)
{
    const float* x       = (const float*)d_in[0];   // [32,128,56,56]
    const float* weight  = (const float*)d_in[1];   // [256,128,3,3]
    const float* bias    = (const float*)d_in[2];   // [256]
    const float* scale_x = (const float*)d_in[3];   // scalar
    // d_in[4] = lut (unused; bf16 HMMA + fp32 accum is exact for these ranges)
    float* out = (float*)d_out;

    cudaFuncSetAttribute(conv_hmma_kernel,
                         cudaFuncAttributeMaxDynamicSharedMemorySize, SMEM_DYN);

    quant_x_kernel<<<NPOS * 4 / 256, 256>>>(x, scale_x);
    quant_w_kernel<<<O_, 128>>>(weight);
    conv_hmma_kernel<<<NPOS / 128, 512, SMEM_DYN>>>(scale_x, bias, out);
}

// round 5
// speedup vs baseline: 2.3056x; 1.0167x over previous
#include <cuda_runtime.h>
#include <cuda_bf16.h>
#include <stdint.h>

// Problem constants
#define B_   32
#define C_   128
#define H_   56
#define W_   56
#define O_   256
#define HW_  (H_*W_)           // 3136
#define NPOS (B_*HW_)          // 100352

// Scratch (__device__ globals, allocation-free rule)
__device__ __align__(16) __nv_bfloat16 g_xb[(size_t)NPOS * C_];     // [pos][c] NHWC bf16
__device__ __align__(16) __nv_bfloat16 g_wb[(size_t)O_ * 9 * C_];   // [o][kp][c] bf16
__device__ float g_sw[O_];

// ---------------------------------------------------------------------------
// PTX helpers (base-ISA only; valid on plain sm_103 target)
// ---------------------------------------------------------------------------
__device__ __forceinline__ void cp16(uint32_t dst, const void* src, uint32_t sz) {
    asm volatile("cp.async.cg.shared.global [%0], [%1], 16, %2;\n"
                 :: "r"(dst), "l"(__cvta_generic_to_global(src)), "r"(sz));
}
__device__ __forceinline__ void cp_commit() { asm volatile("cp.async.commit_group;\n" ::); }
template<int N> __device__ __forceinline__ void cp_wait() {
    asm volatile("cp.async.wait_group %0;\n" :: "n"(N));
}
__device__ __forceinline__ void ldsm4(uint32_t* r, uint32_t addr) {
    asm volatile("ldmatrix.sync.aligned.m8n8.x4.shared.b16 {%0,%1,%2,%3}, [%4];\n"
                 : "=r"(r[0]), "=r"(r[1]), "=r"(r[2]), "=r"(r[3]) : "r"(addr));
}
__device__ __forceinline__ void mma_bf16(float* c, const uint32_t* a, uint32_t b0, uint32_t b1) {
    asm volatile("mma.sync.aligned.m16n8k16.row.col.f32.bf16.bf16.f32 "
                 "{%0,%1,%2,%3}, {%4,%5,%6,%7}, {%8,%9}, {%0,%1,%2,%3};\n"
                 : "+f"(c[0]), "+f"(c[1]), "+f"(c[2]), "+f"(c[3])
                 : "r"(a[0]), "r"(a[1]), "r"(a[2]), "r"(a[3]), "r"(b0), "r"(b1));
}

// ---------------------------------------------------------------------------
// 1) Quantize x: NCHW fp32 -> NHWC bf16 (integer-valued).
//    Lane layout: 32 consecutive positions per channel-group -> every global
//    load is a full 128B line; 4 channel-groups per 64-position block.
// ---------------------------------------------------------------------------
__global__ __launch_bounds__(256) void quant_x_kernel(const float* __restrict__ x,
                                                      const float* __restrict__ sxp)
{
    int t = threadIdx.x;
    float s = *sxp;
    int pos = blockIdx.x * 64 + (t & 63);      // lanes consecutive in pos
    int g   = t >> 6;                          // channel group 0..3 (32 ch)
    int b = pos / HW_, sp = pos - b * HW_;
    const float* xp = x + (size_t)b * C_ * HW_ + (size_t)(g * 32) * HW_ + sp;

    uint32_t pk[16];
#pragma unroll
    for (int j = 0; j < 16; j++) {
        float v0 = xp[(2 * j) * HW_], v1 = xp[(2 * j + 1) * HW_];
        int q0 = (int)rintf(v0 / s); q0 = max(-127, min(127, q0));
        int q1 = (int)rintf(v1 / s); q1 = max(-127, min(127, q1));
        __nv_bfloat162 h = __floats2bfloat162_rn((float)q0, (float)q1);
        pk[j] = *(uint32_t*)&h;
    }
    uint4* dst = (uint4*)(g_xb + (size_t)pos * C_ + g * 32);
#pragma unroll
    for (int q = 0; q < 4; q++)
        dst[q] = make_uint4(pk[4 * q], pk[4 * q + 1], pk[4 * q + 2], pk[4 * q + 3]);
}

// ---------------------------------------------------------------------------
// 2) Weight quantization: per-o scale = max|w|/127, repack [O][C][3][3]->[o][kp][c] bf16
// ---------------------------------------------------------------------------
__global__ __launch_bounds__(128) void quant_w_kernel(const float* __restrict__ w)
{
    int o = blockIdx.x, t = threadIdx.x;
    const float* wo = w + (size_t)o * 1152;

    float m = 0.f;
    for (int i = t; i < 1152; i += 128) m = fmaxf(m, fabsf(wo[i]));
#pragma unroll
    for (int off = 16; off; off >>= 1) m = fmaxf(m, __shfl_xor_sync(0xFFFFFFFFu, m, off));
    __shared__ float red[4];
    if ((t & 31) == 0) red[t >> 5] = m;
    __syncthreads();
    m = fmaxf(fmaxf(red[0], red[1]), fmaxf(red[2], red[3]));
    float scale = m / 127.0f;
    if (t == 0) g_sw[o] = scale;

    for (int i = t; i < 1152; i += 128) {
        int c = i / 9, kp = i - c * 9;
        int q = (int)rintf(wo[i] / scale);
        q = max(-127, min(127, q));
        g_wb[((size_t)o * 9 + kp) * C_ + c] = __float2bfloat16((float)q);
    }
}

// ---------------------------------------------------------------------------
// 3) bf16 HMMA implicit-GEMM conv.
//    CTA: 128 positions x 256 o, 512 threads. Warp (wm,wn): 32 pos x 64 o.
//    18 K-stages of 64 channels (9 taps x 2 halves). 3-stage cp.async ring,
//    ONE __syncthreads per stage, 2-stage prefetch horizon.
// ---------------------------------------------------------------------------
#define ASTRIDE 144
#define ABYTES  (128 * ASTRIDE)       // 18432
#define BBYTES  (256 * ASTRIDE)       // 36864
#define STAGE   (ABYTES + BBYTES)     // 55296
#define NSTG    3
#define SMEM_DYN (NSTG * STAGE)       // 165888

__global__ __launch_bounds__(512)
void conv_hmma_kernel(const float* __restrict__ sxp,
                      const float* __restrict__ bias,
                      float* __restrict__ out)
{
    extern __shared__ char sm[];
    uint32_t sbase = (uint32_t)__cvta_generic_to_shared(sm);
    int t = threadIdx.x;
    int wid = t >> 5, l = t & 31;
    int wm = wid >> 2, wn = wid & 3;
    int s0 = blockIdx.x * 128;

    // Load geometry: thread owns A rows {t>>3, t>>3+64}, 16B chunk jj = t&7
    int jj = t & 7;
    int bA[2], ohA[2], owA[2];
#pragma unroll
    for (int i = 0; i < 2; i++) {
        int r = (t >> 3) + 64 * i;
        int pos = s0 + r;
        int b = pos / HW_, sp = pos - b * HW_;
        bA[i] = b; ohA[i] = sp / W_; owA[i] = sp - ohA[i] * W_;
    }

    float acc[2][8][4];
#pragma unroll
    for (int mi = 0; mi < 2; mi++)
#pragma unroll
        for (int ni = 0; ni < 8; ni++)
#pragma unroll
            for (int q = 0; q < 4; q++) acc[mi][ni][q] = 0.f;

    auto load_stage = [&](int s, int stg) {
        int kp = s >> 1, half = s & 1;
        uint32_t Ab = sbase + stg * STAGE;
        uint32_t Bb = Ab + ABYTES;
        int kh = kp / 3, kw = kp - kh * 3;
        int coff = half * 64 + jj * 8;            // channel offset of this 16B chunk
#pragma unroll
        for (int i = 0; i < 2; i++) {
            int r = (t >> 3) + 64 * i;
            int ih = ohA[i] + kh - 1, iw = owA[i] + kw - 1;
            bool v = ((unsigned)ih < (unsigned)H_) && ((unsigned)iw < (unsigned)W_);
            const __nv_bfloat16* src = v
                ? (g_xb + ((size_t)bA[i] * HW_ + (size_t)ih * W_ + iw) * C_ + coff)
                : g_xb;
            cp16(Ab + r * ASTRIDE + jj * 16, src, v ? 16u : 0u);
        }
#pragma unroll
        for (int i = 0; i < 4; i++) {
            int o = (t >> 3) + 64 * i;
            const __nv_bfloat16* src = g_wb + ((size_t)o * 9 + kp) * C_ + coff;
            cp16(Bb + o * ASTRIDE + jj * 16, src, 16u);
        }
    };

    auto compute_stage = [&](int stg) {
        uint32_t Ab = sbase + stg * STAGE;
        uint32_t Bb = Ab + ABYTES;
        uint32_t aAddr[2], bAddr[4];
#pragma unroll
        for (int mi = 0; mi < 2; mi++) {
            int r = wm * 32 + mi * 16 + (l & 15);
            aAddr[mi] = Ab + r * ASTRIDE + (l >> 4) * 16;
        }
#pragma unroll
        for (int p = 0; p < 4; p++) {
            int o = wn * 64 + p * 16 + (l & 7) + (l >> 4) * 8;
            bAddr[p] = Bb + o * ASTRIDE + ((l >> 3) & 1) * 16;
        }
#pragma unroll
        for (int ks = 0; ks < 4; ks++) {          // 4 x k16 = 64 channels
            uint32_t a[2][4];
            ldsm4(a[0], aAddr[0] + ks * 32);
            ldsm4(a[1], aAddr[1] + ks * 32);
            uint32_t bf[4][4];
#pragma unroll
            for (int p = 0; p < 4; p++) ldsm4(bf[p], bAddr[p] + ks * 32);
#pragma unroll
            for (int mi = 0; mi < 2; mi++)
#pragma unroll
                for (int ni = 0; ni < 8; ni++) {
                    const uint32_t* bb = bf[ni >> 1];
                    uint32_t b0 = (ni & 1) ? bb[2] : bb[0];
                    uint32_t b1 = (ni & 1) ? bb[3] : bb[1];
                    mma_bf16(acc[mi][ni], a[mi], b0, b1);
                }
        }
    };

    // Prologue: prefetch stages 0 and 1 (one commit group each)
    load_stage(0, 0); cp_commit();
    load_stage(1, 1); cp_commit();

#pragma unroll 1
    for (int s = 0; s < 18; s++) {
        cp_wait<1>();          // all groups except newest done -> stage s resident
        __syncthreads();       // everyone past compute(s-1); stage-s data visible
        if (s + 2 < 18) load_stage(s + 2, (s + 2) % NSTG);
        cp_commit();           // empty group in the tail keeps wait-count exact
        compute_stage(s % NSTG);
    }

    // Epilogue: dequant + bias, NCHW out.
    // C frag m16n8: lane l (g=l>>2, tg=l&3): c0=[g][2tg] c1=[g][2tg+1] c2=[g+8][2tg] c3=[g+8][2tg+1]
    float sx = *sxp;
    int g = l >> 2, tg = l & 3;
#pragma unroll
    for (int mi = 0; mi < 2; mi++) {
#pragma unroll
        for (int h = 0; h < 2; h++) {
            int r = wm * 32 + mi * 16 + g + 8 * h;
            int pos = s0 + r;
            int b = pos / HW_, sp = pos - b * HW_;
#pragma unroll
            for (int ni = 0; ni < 8; ni++) {
                int o = wn * 64 + ni * 8 + tg * 2;
                float f0 = acc[mi][ni][h * 2 + 0];
                float f1 = acc[mi][ni][h * 2 + 1];
                out[((size_t)b * O_ + o) * HW_ + sp]     = f0 * (sx * g_sw[o])     + bias[o];
                out[((size_t)b * O_ + o + 1) * HW_ + sp] = f1 * (sx * g_sw[o + 1]) + bias[o + 1];
            }
        }
    }
}

// ---------------------------------------------------------------------------
extern "C" void kernel_launch(void* const* d_in, const int* in_sizes, int n_in,
                              void* d_out, int out_size)
{
    const float* x       = (const float*)d_in[0];   // [32,128,56,56]
    const float* weight  = (const float*)d_in[1];   // [256,128,3,3]
    const float* bias    = (const float*)d_in[2];   // [256]
    const float* scale_x = (const float*)d_in[3];   // scalar
    // d_in[4] = lut (unused; bf16 HMMA + fp32 accum is exact for these ranges)
    float* out = (float*)d_out;

    cudaFuncSetAttribute(conv_hmma_kernel,
                         cudaFuncAttributeMaxDynamicSharedMemorySize, SMEM_DYN);

    quant_x_kernel<<<NPOS / 64, 256>>>(x, scale_x);
    quant_w_kernel<<<O_, 128>>>(weight);
    conv_hmma_kernel<<<NPOS / 128, 512, SMEM_DYN>>>(scale_x, bias, out);
}

// round 6
// speedup vs baseline: 2.4018x; 1.0417x over previous
#include <cuda_runtime.h>
#include <cuda_fp16.h>
#include <stdint.h>

#define B_   32
#define C_   128
#define H_   56
#define W_   56
#define O_   256
#define HW_  3136
#define TROW 28          // tiles per row
#define TPI  784         // tiles per image
#define NT   25088       // total 4x4 tiles (B_*TPI)

// Scratch (__device__ globals, allocation-free rule)
__device__ __align__(16) __half g_V[(size_t)16 * NT * 128];   // [tap][tile][c]  ~103MB
__device__ __align__(16) __half g_U[(size_t)16 * O_ * 128];   // [tap][o][c]     1MB
__device__ float g_sw[O_];

// ---------------------------------------------------------------------------
// PTX helpers (base ISA, valid on plain sm_103 target)
// ---------------------------------------------------------------------------
__device__ __forceinline__ void cp16(uint32_t dst, const void* src) {
    asm volatile("cp.async.cg.shared.global [%0], [%1], 16;\n"
                 :: "r"(dst), "l"(__cvta_generic_to_global(src)));
}
__device__ __forceinline__ void cp_commit() { asm volatile("cp.async.commit_group;\n" ::); }
template<int N> __device__ __forceinline__ void cp_wait() {
    asm volatile("cp.async.wait_group %0;\n" :: "n"(N));
}
__device__ __forceinline__ void ldsm4(uint32_t* r, uint32_t addr) {
    asm volatile("ldmatrix.sync.aligned.m8n8.x4.shared.b16 {%0,%1,%2,%3}, [%4];\n"
                 : "=r"(r[0]), "=r"(r[1]), "=r"(r[2]), "=r"(r[3]) : "r"(addr));
}
__device__ __forceinline__ void mma_f16(float* c, const uint32_t* a, uint32_t b0, uint32_t b1) {
    asm volatile("mma.sync.aligned.m16n8k16.row.col.f32.f16.f16.f32 "
                 "{%0,%1,%2,%3}, {%4,%5,%6,%7}, {%8,%9}, {%0,%1,%2,%3};\n"
                 : "+f"(c[0]), "+f"(c[1]), "+f"(c[2]), "+f"(c[3])
                 : "r"(a[0]), "r"(a[1]), "r"(a[2]), "r"(a[3]), "r"(b0), "r"(b1));
}

// ---------------------------------------------------------------------------
// 1) x -> quantize -> Winograd input transform -> g_V[tap][tile][c] (fp16 exact:
//    V entries are integers |.| <= 508). CTA per (image, tile-row): stages 4
//    input rows x 128 ch in SMEM (quantized), then transforms 28 tiles.
// ---------------------------------------------------------------------------
#define XSM_STRIDE 58    // halfs per (row,c) line; odd word stride
#define XSMEM (4 * 128 * XSM_STRIDE * 2)   // 59392 B

__global__ __launch_bounds__(256) void wino_x_kernel(const float* __restrict__ x,
                                                     const float* __restrict__ sxp)
{
    extern __shared__ __half sq[];
    int t = threadIdx.x;
    int bi = blockIdx.x / TROW, ti = blockIdx.x % TROW;
    float s = *sxp;

    // Load + quantize: 4 rows (2ti-1..2ti+2) x 128 ch x 56 w
#pragma unroll 4
    for (int i = 0; i < 28; i++) {
        int idx = t + 256 * i;             // 0..7167 = 4*128*14-1
        int w4 = idx % 14;
        int cr = idx / 14;
        int c = cr & 127, j = cr >> 7;
        int row = 2 * ti - 1 + j;
        float4 v = make_float4(0.f, 0.f, 0.f, 0.f);
        if (row >= 0 && row < H_)
            v = *(const float4*)(x + ((size_t)bi * C_ + c) * HW_ + row * W_ + w4 * 4);
        float q0 = fminf(fmaxf(rintf(v.x / s), -127.f), 127.f);
        float q1 = fminf(fmaxf(rintf(v.y / s), -127.f), 127.f);
        float q2 = fminf(fmaxf(rintf(v.z / s), -127.f), 127.f);
        float q3 = fminf(fmaxf(rintf(v.w / s), -127.f), 127.f);
        __half2* dst = (__half2*)(sq + (j * 128 + c) * XSM_STRIDE + w4 * 4);
        dst[0] = __floats2half2_rn(q0, q1);
        dst[1] = __floats2half2_rn(q2, q3);
    }
    __syncthreads();

    // Transform: item = (tj, c)
#pragma unroll 2
    for (int i = 0; i < 14; i++) {
        int idx = t + 256 * i;             // 0..3583
        int c = idx & 127, tj = idx >> 7;
        float d[4][4];
#pragma unroll
        for (int r = 0; r < 4; r++)
#pragma unroll
            for (int wc = 0; wc < 4; wc++) {
                int w = 2 * tj - 1 + wc;
                d[r][wc] = (w >= 0 && w < W_)
                    ? __half2float(sq[(r * 128 + c) * XSM_STRIDE + w]) : 0.f;
            }
        float e[4][4];
#pragma unroll
        for (int j = 0; j < 4; j++) {
            e[0][j] = d[0][j] - d[2][j];
            e[1][j] = d[1][j] + d[2][j];
            e[2][j] = d[2][j] - d[1][j];
            e[3][j] = d[1][j] - d[3][j];
        }
        float vv[4][4];
#pragma unroll
        for (int r = 0; r < 4; r++) {
            vv[r][0] = e[r][0] - e[r][2];
            vv[r][1] = e[r][1] + e[r][2];
            vv[r][2] = e[r][2] - e[r][1];
            vv[r][3] = e[r][1] - e[r][3];
        }
        int tid = bi * TPI + ti * TROW + tj;
#pragma unroll
        for (int r = 0; r < 4; r++)
#pragma unroll
            for (int j = 0; j < 4; j++)
                g_V[((size_t)(r * 4 + j) * NT + tid) * 128 + c] = __float2half_rn(vv[r][j]);
    }
}

// ---------------------------------------------------------------------------
// 2) weight: per-o dynamic scale = max|w|/127, quantize, Winograd filter
//    transform -> g_U[tap][o][c]  (fp16 exact: quarter-multiples, |.| <= 286)
// ---------------------------------------------------------------------------
__global__ __launch_bounds__(128) void wino_w_kernel(const float* __restrict__ w)
{
    int o = blockIdx.x, t = threadIdx.x;
    const float* wo = w + (size_t)o * 1152;

    float m = 0.f;
    for (int i = t; i < 1152; i += 128) m = fmaxf(m, fabsf(wo[i]));
#pragma unroll
    for (int off = 16; off; off >>= 1) m = fmaxf(m, __shfl_xor_sync(0xFFFFFFFFu, m, off));
    __shared__ float red[4];
    if ((t & 31) == 0) red[t >> 5] = m;
    __syncthreads();
    m = fmaxf(fmaxf(red[0], red[1]), fmaxf(red[2], red[3]));
    float scale = m / 127.0f;
    if (t == 0) g_sw[o] = scale;

    int c = t;   // 128 threads == 128 channels
    float g[3][3];
#pragma unroll
    for (int kh = 0; kh < 3; kh++)
#pragma unroll
        for (int kw = 0; kw < 3; kw++) {
            float q = rintf(wo[c * 9 + kh * 3 + kw] / scale);
            g[kh][kw] = fminf(fmaxf(q, -127.f), 127.f);
        }
    float f[4][3];
#pragma unroll
    for (int j = 0; j < 3; j++) {
        f[0][j] = g[0][j];
        f[1][j] = (g[0][j] + g[1][j] + g[2][j]) * 0.5f;
        f[2][j] = (g[0][j] - g[1][j] + g[2][j]) * 0.5f;
        f[3][j] = g[2][j];
    }
#pragma unroll
    for (int r = 0; r < 4; r++) {
        float u0 = f[r][0];
        float u1 = (f[r][0] + f[r][1] + f[r][2]) * 0.5f;
        float u2 = (f[r][0] - f[r][1] + f[r][2]) * 0.5f;
        float u3 = f[r][2];
        g_U[((size_t)(r * 4 + 0) * O_ + o) * 128 + c] = __float2half_rn(u0);
        g_U[((size_t)(r * 4 + 1) * O_ + o) * 128 + c] = __float2half_rn(u1);
        g_U[((size_t)(r * 4 + 2) * O_ + o) * 128 + c] = __float2half_rn(u2);
        g_U[((size_t)(r * 4 + 3) * O_ + o) * 128 + c] = __float2half_rn(u3);
    }
}

// ---------------------------------------------------------------------------
// 3) Winograd GEMM: 16 taps, K=128 each. CTA = 64 tiles x 64 o, 512 threads
//    (16 warps 4x4, warp = 16 tiles x 16 o). Taps pipelined as a 3-stage
//    cp.async ring; output transform folded incrementally into 32 fp32
//    accumulators/thread (coeffs {0,+-1}, taps fully unrolled).
// ---------------------------------------------------------------------------
#define GSTRIDE 272                       // bytes per 256B row (+16 pad)
#define GABYTES (64 * GSTRIDE)            // 17408
#define GSTAGE  (2 * GABYTES)             // 34816
#define GSMEM   (3 * GSTAGE)              // 104448 (>= epilogue 66816)

__global__ __launch_bounds__(512)
void wino_gemm_kernel(const float* __restrict__ sxp,
                      const float* __restrict__ bias,
                      float* __restrict__ out)
{
    extern __shared__ char sm[];
    uint32_t sbase = (uint32_t)__cvta_generic_to_shared(sm);
    int t = threadIdx.x;
    int wid = t >> 5, l = t & 31;
    int wm = wid & 3, wn = wid >> 2;      // warp tile: tiles [16*wm), o [16*wn)
    int o0 = blockIdx.x * 64;             // o-block fastest -> V shared in L2
    int tid0 = blockIdx.y * 64;

    float oacc[2][4][4];
#pragma unroll
    for (int n = 0; n < 2; n++)
#pragma unroll
        for (int q = 0; q < 4; q++)
#pragma unroll
            for (int e = 0; e < 4; e++) oacc[n][q][e] = 0.f;

    // ldsm base addresses (per stage add stg*GSTAGE)
    uint32_t aOff = (uint32_t)((wm * 16 + (l & 15)) * GSTRIDE + (l >> 4) * 16);
    uint32_t bOff = (uint32_t)(GABYTES + (wn * 16 + (l & 7) + (l >> 4) * 8) * GSTRIDE
                               + ((l >> 3) & 1) * 16);

    auto load_stage = [&](int tap, int stg) {
        const __half* Vs = g_V + ((size_t)tap * NT + tid0) * 128;
        const __half* Us = g_U + ((size_t)tap * O_ + o0) * 128;
        uint32_t base = sbase + stg * GSTAGE;
#pragma unroll
        for (int i = 0; i < 2; i++) {
            int idx = t + 512 * i;        // 0..1023
            int row = idx >> 4, jj = idx & 15;
            cp16(base + row * GSTRIDE + jj * 16, Vs + row * 128 + jj * 8);
        }
#pragma unroll
        for (int i = 0; i < 2; i++) {
            int idx = t + 512 * i;
            int row = idx >> 4, jj = idx & 15;
            cp16(base + GABYTES + row * GSTRIDE + jj * 16, Us + row * 128 + jj * 8);
        }
    };

    const float AT0[4] = {1.f, 1.f, 1.f, 0.f};
    const float AT1[4] = {0.f, 1.f, -1.f, -1.f};

    load_stage(0, 0); cp_commit();
    load_stage(1, 1); cp_commit();

#pragma unroll
    for (int tap = 0; tap < 16; tap++) {
        cp_wait<1>();
        __syncthreads();
        if (tap + 2 < 16) load_stage(tap + 2, (tap + 2) % 3);
        cp_commit();

        uint32_t base = sbase + (tap % 3) * GSTAGE;
        float mfr[2][4] = {{0.f,0.f,0.f,0.f},{0.f,0.f,0.f,0.f}};
#pragma unroll
        for (int ks = 0; ks < 8; ks++) {
            uint32_t a[4], bf[4];
            ldsm4(a,  base + aOff + ks * 32);
            ldsm4(bf, base + bOff + ks * 32);
            mma_f16(mfr[0], a, bf[0], bf[1]);
            mma_f16(mfr[1], a, bf[2], bf[3]);
        }
        // Incremental output transform: out_xy += AT[x][i]*AT[y][j] * Mhat_ij
        int i_ = tap >> 2, j_ = tap & 3;
        float c00 = AT0[i_] * AT0[j_];
        float c01 = AT0[i_] * AT1[j_];
        float c10 = AT1[i_] * AT0[j_];
        float c11 = AT1[i_] * AT1[j_];
#pragma unroll
        for (int n = 0; n < 2; n++)
#pragma unroll
            for (int q = 0; q < 4; q++) {
                float v = mfr[n][q];
                oacc[n][q][0] += c00 * v;
                oacc[n][q][1] += c01 * v;
                oacc[n][q][2] += c10 * v;
                oacc[n][q][3] += c11 * v;
            }
    }

    // Epilogue: stage in SMEM for coalesced NCHW writes
    __syncthreads();
    float* ep = (float*)sm;               // [64 tiles][261] floats
    int g = l >> 2, tg = l & 3;
#pragma unroll
    for (int n = 0; n < 2; n++)
#pragma unroll
        for (int q = 0; q < 4; q++) {
            int tl = wm * 16 + g + (q >> 1) * 8;
            int ol = wn * 16 + n * 8 + tg * 2 + (q & 1);
#pragma unroll
            for (int e = 0; e < 4; e++)
                ep[tl * 261 + ol * 4 + e] = oacc[n][q][e];
        }
    __syncthreads();

    float sx = *sxp;
    int xx   = (t >> 7) & 1;
    int tile = (t >> 1) & 63;
    int y    = t & 1;
    int ohi  = t >> 8;
    int tidg = tid0 + tile;
    int b  = tidg / TPI;
    int rr = tidg - b * TPI;
    int ti = rr / TROW, tj = rr - ti * TROW;
    size_t obase = (size_t)b * O_ * HW_ + (2 * ti + xx) * W_ + 2 * tj + y;
#pragma unroll 4
    for (int v = 0; v < 32; v++) {
        int ol = 2 * v + ohi;
        int o = o0 + ol;
        float val = ep[tile * 261 + ol * 4 + xx * 2 + y];
        out[obase + (size_t)o * HW_] = val * (sx * g_sw[o]) + bias[o];
    }
}

// ---------------------------------------------------------------------------
extern "C" void kernel_launch(void* const* d_in, const int* in_sizes, int n_in,
                              void* d_out, int out_size)
{
    const float* x       = (const float*)d_in[0];   // [32,128,56,56]
    const float* weight  = (const float*)d_in[1];   // [256,128,3,3]
    const float* bias    = (const float*)d_in[2];   // [256]
    const float* scale_x = (const float*)d_in[3];   // scalar
    // d_in[4] = lut (unused; fp16 Winograd arithmetic is exact for int8 data)
    float* out = (float*)d_out;

    cudaFuncSetAttribute(wino_x_kernel,
                         cudaFuncAttributeMaxDynamicSharedMemorySize, XSMEM);
    cudaFuncSetAttribute(wino_gemm_kernel,
                         cudaFuncAttributeMaxDynamicSharedMemorySize, GSMEM);

    wino_x_kernel<<<B_ * TROW, 256, XSMEM>>>(x, scale_x);
    wino_w_kernel<<<O_, 128>>>(weight);
    wino_gemm_kernel<<<dim3(4, NT / 64), 512, GSMEM>>>(scale_x, bias, out);
}

// round 7
// speedup vs baseline: 2.6932x; 1.1213x over previous
#include <cuda_runtime.h>
#include <cuda_fp16.h>
#include <stdint.h>

#define B_   32
#define C_   128
#define H_   56
#define W_   56
#define O_   256
#define HW_  3136
#define TROW 28          // tiles per row
#define TPI  784         // tiles per image
#define NT   25088       // total 4x4 tiles (B_*TPI)

// Scratch (__device__ globals, allocation-free rule)
__device__ __align__(16) __half g_V[(size_t)16 * NT * 128];   // [tap][tile][c]  ~103MB
__device__ __align__(16) __half g_U[(size_t)16 * O_ * 128];   // [tap][o][c]     1MB
__device__ float g_sw[O_];

// ---------------------------------------------------------------------------
// PTX helpers (base ISA, valid on plain sm_103 target)
// ---------------------------------------------------------------------------
__device__ __forceinline__ void cp16(uint32_t dst, const void* src) {
    asm volatile("cp.async.cg.shared.global [%0], [%1], 16;\n"
                 :: "r"(dst), "l"(__cvta_generic_to_global(src)));
}
__device__ __forceinline__ void cp_commit() { asm volatile("cp.async.commit_group;\n" ::); }
template<int N> __device__ __forceinline__ void cp_wait() {
    asm volatile("cp.async.wait_group %0;\n" :: "n"(N));
}
__device__ __forceinline__ void ldsm4(uint32_t* r, uint32_t addr) {
    asm volatile("ldmatrix.sync.aligned.m8n8.x4.shared.b16 {%0,%1,%2,%3}, [%4];\n"
                 : "=r"(r[0]), "=r"(r[1]), "=r"(r[2]), "=r"(r[3]) : "r"(addr));
}
__device__ __forceinline__ void mma_f16(float* c, const uint32_t* a, uint32_t b0, uint32_t b1) {
    asm volatile("mma.sync.aligned.m16n8k16.row.col.f32.f16.f16.f32 "
                 "{%0,%1,%2,%3}, {%4,%5,%6,%7}, {%8,%9}, {%0,%1,%2,%3};\n"
                 : "+f"(c[0]), "+f"(c[1]), "+f"(c[2]), "+f"(c[3])
                 : "r"(a[0]), "r"(a[1]), "r"(a[2]), "r"(a[3]), "r"(b0), "r"(b1));
}

// ---------------------------------------------------------------------------
// 1) x -> quantize -> Winograd input transform -> g_V[tap][tile][c].
//    Quantized rows cached in SMEM as int8 (30KB -> 7 CTAs/SM, 87% occ).
//    V entries are integers |.| <= 508 -> exact in fp16.
// ---------------------------------------------------------------------------
#define XSTRIDE 60       // bytes per (row,c) line
#define XSMEM (4 * 128 * XSTRIDE)   // 30720 B

__global__ __launch_bounds__(256) void wino_x_kernel(const float* __restrict__ x,
                                                     const float* __restrict__ sxp)
{
    extern __shared__ int8_t sq[];
    int t = threadIdx.x;
    int bi = blockIdx.x / TROW, ti = blockIdx.x % TROW;
    float s = *sxp;

    // Load + quantize: 4 rows (2ti-1..2ti+2) x 128 ch x 56 w -> int8 smem
#pragma unroll 4
    for (int i = 0; i < 28; i++) {
        int idx = t + 256 * i;             // 0..7167 = 4*128*14-1
        int w4 = idx % 14;
        int cr = idx / 14;
        int c = cr & 127, j = cr >> 7;
        int row = 2 * ti - 1 + j;
        float4 v = make_float4(0.f, 0.f, 0.f, 0.f);
        if (row >= 0 && row < H_)
            v = *(const float4*)(x + ((size_t)bi * C_ + c) * HW_ + row * W_ + w4 * 4);
        int q0 = (int)fminf(fmaxf(rintf(v.x / s), -127.f), 127.f);
        int q1 = (int)fminf(fmaxf(rintf(v.y / s), -127.f), 127.f);
        int q2 = (int)fminf(fmaxf(rintf(v.z / s), -127.f), 127.f);
        int q3 = (int)fminf(fmaxf(rintf(v.w / s), -127.f), 127.f);
        uint32_t pk = (uint32_t)(q0 & 0xFF) | ((uint32_t)(q1 & 0xFF) << 8)
                    | ((uint32_t)(q2 & 0xFF) << 16) | ((uint32_t)(q3 & 0xFF) << 24);
        *(uint32_t*)(sq + (j * 128 + c) * XSTRIDE + w4 * 4) = pk;
    }
    __syncthreads();

    // Transform: item = (tj, c)
#pragma unroll 2
    for (int i = 0; i < 14; i++) {
        int idx = t + 256 * i;             // 0..3583
        int c = idx & 127, tj = idx >> 7;
        float d[4][4];
#pragma unroll
        for (int r = 0; r < 4; r++)
#pragma unroll
            for (int wc = 0; wc < 4; wc++) {
                int w = 2 * tj - 1 + wc;
                d[r][wc] = (w >= 0 && w < W_)
                    ? (float)sq[(r * 128 + c) * XSTRIDE + w] : 0.f;
            }
        float e[4][4];
#pragma unroll
        for (int j = 0; j < 4; j++) {
            e[0][j] = d[0][j] - d[2][j];
            e[1][j] = d[1][j] + d[2][j];
            e[2][j] = d[2][j] - d[1][j];
            e[3][j] = d[1][j] - d[3][j];
        }
        float vv[4][4];
#pragma unroll
        for (int r = 0; r < 4; r++) {
            vv[r][0] = e[r][0] - e[r][2];
            vv[r][1] = e[r][1] + e[r][2];
            vv[r][2] = e[r][2] - e[r][1];
            vv[r][3] = e[r][1] - e[r][3];
        }
        int tid = bi * TPI + ti * TROW + tj;
#pragma unroll
        for (int r = 0; r < 4; r++)
#pragma unroll
            for (int j = 0; j < 4; j++)
                g_V[((size_t)(r * 4 + j) * NT + tid) * 128 + c] = __float2half_rn(vv[r][j]);
    }
}

// ---------------------------------------------------------------------------
// 2) weight: per-o dynamic scale = max|w|/127, quantize, Winograd filter
//    transform -> g_U[tap][o][c]  (fp16 exact: quarter-multiples, |.| <= 286)
// ---------------------------------------------------------------------------
__global__ __launch_bounds__(128) void wino_w_kernel(const float* __restrict__ w)
{
    int o = blockIdx.x, t = threadIdx.x;
    const float* wo = w + (size_t)o * 1152;

    float m = 0.f;
    for (int i = t; i < 1152; i += 128) m = fmaxf(m, fabsf(wo[i]));
#pragma unroll
    for (int off = 16; off; off >>= 1) m = fmaxf(m, __shfl_xor_sync(0xFFFFFFFFu, m, off));
    __shared__ float red[4];
    if ((t & 31) == 0) red[t >> 5] = m;
    __syncthreads();
    m = fmaxf(fmaxf(red[0], red[1]), fmaxf(red[2], red[3]));
    float scale = m / 127.0f;
    if (t == 0) g_sw[o] = scale;

    int c = t;   // 128 threads == 128 channels
    float g[3][3];
#pragma unroll
    for (int kh = 0; kh < 3; kh++)
#pragma unroll
        for (int kw = 0; kw < 3; kw++) {
            float q = rintf(wo[c * 9 + kh * 3 + kw] / scale);
            g[kh][kw] = fminf(fmaxf(q, -127.f), 127.f);
        }
    float f[4][3];
#pragma unroll
    for (int j = 0; j < 3; j++) {
        f[0][j] = g[0][j];
        f[1][j] = (g[0][j] + g[1][j] + g[2][j]) * 0.5f;
        f[2][j] = (g[0][j] - g[1][j] + g[2][j]) * 0.5f;
        f[3][j] = g[2][j];
    }
#pragma unroll
    for (int r = 0; r < 4; r++) {
        float u0 = f[r][0];
        float u1 = (f[r][0] + f[r][1] + f[r][2]) * 0.5f;
        float u2 = (f[r][0] - f[r][1] + f[r][2]) * 0.5f;
        float u3 = f[r][2];
        g_U[((size_t)(r * 4 + 0) * O_ + o) * 128 + c] = __float2half_rn(u0);
        g_U[((size_t)(r * 4 + 1) * O_ + o) * 128 + c] = __float2half_rn(u1);
        g_U[((size_t)(r * 4 + 2) * O_ + o) * 128 + c] = __float2half_rn(u2);
        g_U[((size_t)(r * 4 + 3) * O_ + o) * 128 + c] = __float2half_rn(u3);
    }
}

// ---------------------------------------------------------------------------
// 3) Winograd GEMM: 16 taps, K=128 each. CTA = 128 tiles x 64 o, 512 threads
//    (16 warps 4x4, warp = 32 tiles x 16 o). Taps as 3-stage cp.async ring;
//    output transform folded incrementally into 64 fp32 accumulators/thread.
// ---------------------------------------------------------------------------
#define GSTRIDE 272                       // bytes per 256B row (+16 pad)
#define GABYTES (128 * GSTRIDE)           // 34816
#define GBBYTES (64 * GSTRIDE)            // 17408
#define GSTAGE  (GABYTES + GBBYTES)       // 52224
#define GSMEM   (3 * GSTAGE)              // 156672 (>= epilogue 133632)

__global__ __launch_bounds__(512)
void wino_gemm_kernel(const float* __restrict__ sxp,
                      const float* __restrict__ bias,
                      float* __restrict__ out)
{
    extern __shared__ char sm[];
    uint32_t sbase = (uint32_t)__cvta_generic_to_shared(sm);
    int t = threadIdx.x;
    int wid = t >> 5, l = t & 31;
    int wm = wid & 3, wn = wid >> 2;      // warp tile: 32 tiles x 16 o
    int o0 = blockIdx.x * 64;             // o-block fastest -> V shared in L2
    int tid0 = blockIdx.y * 128;

    float oacc[2][2][4][4];               // [mi][ni][q][e]
#pragma unroll
    for (int mi = 0; mi < 2; mi++)
#pragma unroll
        for (int ni = 0; ni < 2; ni++)
#pragma unroll
            for (int q = 0; q < 4; q++)
#pragma unroll
                for (int e = 0; e < 4; e++) oacc[mi][ni][q][e] = 0.f;

    // ldsm base addresses (per stage add stg*GSTAGE)
    uint32_t aOff0 = (uint32_t)((wm * 32 + (l & 15)) * GSTRIDE + (l >> 4) * 16);
    uint32_t aOff1 = aOff0 + 16u * GSTRIDE;
    uint32_t bOff  = (uint32_t)(GABYTES + (wn * 16 + (l & 7) + (l >> 4) * 8) * GSTRIDE
                                + ((l >> 3) & 1) * 16);

    auto load_stage = [&](int tap, int stg) {
        const __half* Vs = g_V + ((size_t)tap * NT + tid0) * 128;
        const __half* Us = g_U + ((size_t)tap * O_ + o0) * 128;
        uint32_t base = sbase + stg * GSTAGE;
#pragma unroll
        for (int i = 0; i < 4; i++) {
            int idx = t + 512 * i;        // 0..2047 -> A: 128 rows x 16 chunks
            int row = idx >> 4, jj = idx & 15;
            cp16(base + row * GSTRIDE + jj * 16, Vs + row * 128 + jj * 8);
        }
#pragma unroll
        for (int i = 0; i < 2; i++) {
            int idx = t + 512 * i;        // 0..1023 -> B: 64 rows x 16 chunks
            int row = idx >> 4, jj = idx & 15;
            cp16(base + GABYTES + row * GSTRIDE + jj * 16, Us + row * 128 + jj * 8);
        }
    };

    const float AT0[4] = {1.f, 1.f, 1.f, 0.f};
    const float AT1[4] = {0.f, 1.f, -1.f, -1.f};

    load_stage(0, 0); cp_commit();
    load_stage(1, 1); cp_commit();

#pragma unroll
    for (int tap = 0; tap < 16; tap++) {
        cp_wait<1>();
        __syncthreads();
        if (tap + 2 < 16) load_stage(tap + 2, (tap + 2) % 3);
        cp_commit();

        uint32_t base = sbase + (tap % 3) * GSTAGE;
        float mfr[2][2][4] = {};
#pragma unroll
        for (int ks = 0; ks < 8; ks++) {
            uint32_t a0[4], a1[4], bf[4];
            ldsm4(a0, base + aOff0 + ks * 32);
            ldsm4(a1, base + aOff1 + ks * 32);
            ldsm4(bf, base + bOff  + ks * 32);
            mma_f16(mfr[0][0], a0, bf[0], bf[1]);
            mma_f16(mfr[0][1], a0, bf[2], bf[3]);
            mma_f16(mfr[1][0], a1, bf[0], bf[1]);
            mma_f16(mfr[1][1], a1, bf[2], bf[3]);
        }
        // Incremental output transform: out_xy += AT[x][i]*AT[y][j] * Mhat_ij
        int i_ = tap >> 2, j_ = tap & 3;
        float c00 = AT0[i_] * AT0[j_];
        float c01 = AT0[i_] * AT1[j_];
        float c10 = AT1[i_] * AT0[j_];
        float c11 = AT1[i_] * AT1[j_];
#pragma unroll
        for (int mi = 0; mi < 2; mi++)
#pragma unroll
            for (int ni = 0; ni < 2; ni++)
#pragma unroll
                for (int q = 0; q < 4; q++) {
                    float v = mfr[mi][ni][q];
                    oacc[mi][ni][q][0] += c00 * v;
                    oacc[mi][ni][q][1] += c01 * v;
                    oacc[mi][ni][q][2] += c10 * v;
                    oacc[mi][ni][q][3] += c11 * v;
                }
    }

    // Epilogue: stage in SMEM for coalesced NCHW writes
    __syncthreads();
    float* ep = (float*)sm;               // [128 tiles][261] floats
    int g = l >> 2, tg = l & 3;
#pragma unroll
    for (int mi = 0; mi < 2; mi++)
#pragma unroll
        for (int ni = 0; ni < 2; ni++)
#pragma unroll
            for (int q = 0; q < 4; q++) {
                int tl = wm * 32 + mi * 16 + g + (q >> 1) * 8;
                int ol = wn * 16 + ni * 8 + tg * 2 + (q & 1);
#pragma unroll
                for (int e = 0; e < 4; e++)
                    ep[tl * 261 + ol * 4 + e] = oacc[mi][ni][q][e];
            }
    __syncthreads();

    float sx = *sxp;
    int tile = t >> 2;                    // 0..127
    int xx   = (t >> 1) & 1;
    int y    = t & 1;
    int tidg = tid0 + tile;
    int b  = tidg / TPI;
    int rr = tidg - b * TPI;
    int ti = rr / TROW, tj = rr - ti * TROW;
    size_t obase = (size_t)b * O_ * HW_ + (2 * ti + xx) * W_ + 2 * tj + y;
#pragma unroll 8
    for (int ol = 0; ol < 64; ol++) {
        int o = o0 + ol;
        float val = ep[tile * 261 + ol * 4 + xx * 2 + y];
        out[obase + (size_t)o * HW_] = val * (sx * g_sw[o]) + bias[o];
    }
}

// ---------------------------------------------------------------------------
extern "C" void kernel_launch(void* const* d_in, const int* in_sizes, int n_in,
                              void* d_out, int out_size)
{
    const float* x       = (const float*)d_in[0];   // [32,128,56,56]
    const float* weight  = (const float*)d_in[1];   // [256,128,3,3]
    const float* bias    = (const float*)d_in[2];   // [256]
    const float* scale_x = (const float*)d_in[3];   // scalar
    // d_in[4] = lut (unused; fp16 Winograd arithmetic is exact for int8 data)
    float* out = (float*)d_out;

    cudaFuncSetAttribute(wino_x_kernel,
                         cudaFuncAttributeMaxDynamicSharedMemorySize, XSMEM);
    cudaFuncSetAttribute(wino_gemm_kernel,
                         cudaFuncAttributeMaxDynamicSharedMemorySize, GSMEM);

    wino_x_kernel<<<B_ * TROW, 256, XSMEM>>>(x, scale_x);
    wino_w_kernel<<<O_, 128>>>(weight);
    wino_gemm_kernel<<<dim3(4, NT / 128), 512, GSMEM>>>(scale_x, bias, out);
}